// round 9
// baseline (speedup 1.0000x reference)
#include <cuda_runtime.h>
#include <cstdint>

// RegressionLoss: masked SmoothL1 (beta=0.5) sum over N=16,777,216.
//   d = outs - labels; ad = |d|
//   sl1 = ad < 0.5 ? d*d : ad - 0.25
//   keep if ad >= 1/len  (lens int32 on device; JAX x64 off)
//   out[0] = sum(keep ? sl1 : 0)
//
// HBM-bound (192 MiB reads). R7: 32.3us kernel, DRAM=80.3%.
// This round: unroll-2 (6 LDG.128 in flight/thread), single wave (888 blocks
// @ occ 6), fused last-block finalize (no zero kernel, no second launch).

#define NBLOCKS 888          // 148 SMs * occ 6 -> exactly one wave
#define NTHREADS 256

__device__ float    g_partial[NBLOCKS];
__device__ unsigned g_count;   // zero-initialized at module load; self-resets

__device__ __forceinline__ float sl1_masked(float o, float l, float lenf) {
    float d  = o - l;
    float ad = fabsf(d);
    float v  = (ad < 0.5f) ? (d * d) : (ad - 0.25f);
    // ad >= 1/len  <=>  ad*len >= 1  (len in [1,1000]; ~1ulp edge noise)
    return (ad * lenf >= 1.0f) ? v : 0.0f;
}

__global__ __launch_bounds__(NTHREADS, 6)
void smoothl1_masked_sum_kernel(const float4* __restrict__ outs4,
                                const float4* __restrict__ labels4,
                                const int4*   __restrict__ lens4,
                                const float*  __restrict__ outs,
                                const float*  __restrict__ labels,
                                const int*    __restrict__ lens,
                                float* __restrict__ out,
                                int nvec, int n, int nblocks) {
    float acc = 0.0f;
    const int stride = gridDim.x * blockDim.x;
    int i = blockIdx.x * blockDim.x + threadIdx.x;

    // unroll-2: 6 independent LDG.128 batched per iteration
    for (; i + stride < nvec; i += 2 * stride) {
        float4 o0 = outs4[i];
        float4 l0 = labels4[i];
        int4   L0 = lens4[i];
        float4 o1 = outs4[i + stride];
        float4 l1 = labels4[i + stride];
        int4   L1 = lens4[i + stride];
        acc += sl1_masked(o0.x, l0.x, (float)L0.x);
        acc += sl1_masked(o0.y, l0.y, (float)L0.y);
        acc += sl1_masked(o0.z, l0.z, (float)L0.z);
        acc += sl1_masked(o0.w, l0.w, (float)L0.w);
        acc += sl1_masked(o1.x, l1.x, (float)L1.x);
        acc += sl1_masked(o1.y, l1.y, (float)L1.y);
        acc += sl1_masked(o1.z, l1.z, (float)L1.z);
        acc += sl1_masked(o1.w, l1.w, (float)L1.w);
    }
    // leftover vec4 iteration
    for (; i < nvec; i += stride) {
        float4 o = outs4[i];
        float4 l = labels4[i];
        int4   L = lens4[i];
        acc += sl1_masked(o.x, l.x, (float)L.x);
        acc += sl1_masked(o.y, l.y, (float)L.y);
        acc += sl1_masked(o.z, l.z, (float)L.z);
        acc += sl1_masked(o.w, l.w, (float)L.w);
    }
    // scalar tail (n not divisible by 4)
    int t = nvec * 4 + blockIdx.x * blockDim.x + threadIdx.x;
    if (t < n) acc += sl1_masked(outs[t], labels[t], (float)lens[t]);

    // ---- block reduction ----
    #pragma unroll
    for (int off = 16; off > 0; off >>= 1)
        acc += __shfl_xor_sync(0xffffffffu, acc, off);

    __shared__ float warp_sums[8];
    __shared__ bool  is_last;
    int lane = threadIdx.x & 31;
    int wid  = threadIdx.x >> 5;
    if (lane == 0) warp_sums[wid] = acc;
    __syncthreads();

    if (wid == 0) {
        float v = (lane < 8) ? warp_sums[lane] : 0.0f;
        #pragma unroll
        for (int off = 4; off > 0; off >>= 1)
            v += __shfl_xor_sync(0xffffffffu, v, off);
        if (lane == 0) {
            g_partial[blockIdx.x] = v;
            __threadfence();
            unsigned prev = atomicAdd(&g_count, 1u);
            is_last = (prev == (unsigned)(nblocks - 1));
        }
    }
    __syncthreads();

    // ---- last block finalizes ----
    if (is_last) {
        __threadfence();
        float s = 0.0f;
        for (int j = threadIdx.x; j < nblocks; j += blockDim.x)
            s += g_partial[j];
        #pragma unroll
        for (int off = 16; off > 0; off >>= 1)
            s += __shfl_xor_sync(0xffffffffu, s, off);
        if (lane == 0) warp_sums[wid] = s;
        __syncthreads();
        if (wid == 0) {
            float v = (lane < 8) ? warp_sums[lane] : 0.0f;
            #pragma unroll
            for (int off = 4; off > 0; off >>= 1)
                v += __shfl_xor_sync(0xffffffffu, v, off);
            if (lane == 0) {
                out[0]  = v;
                g_count = 0u;   // reset for next (graph-replayed) call
            }
        }
    }
}

extern "C" void kernel_launch(void* const* d_in, const int* in_sizes, int n_in,
                              void* d_out, int out_size) {
    const float* outs   = (const float*)d_in[0];
    const float* labels = (const float*)d_in[1];
    const int*   lens   = (const int*)d_in[2];
    float* out = (float*)d_out;
    const int n    = in_sizes[0];
    const int nvec = n >> 2;

    int blocks = NBLOCKS;
    int max_blocks = (nvec + NTHREADS - 1) / NTHREADS;
    if (blocks > max_blocks && max_blocks > 0) blocks = max_blocks;
    if (blocks < 1) blocks = 1;

    smoothl1_masked_sum_kernel<<<blocks, NTHREADS>>>(
        (const float4*)outs, (const float4*)labels, (const int4*)lens,
        outs, labels, lens, out, nvec, n, blocks);
}